// round 1
// baseline (speedup 1.0000x reference)
#include <cuda_runtime.h>
#include <cuda_bf16.h>

// Problem shape (fixed by the dataset)
#define BB 32
#define AA 32768
#define CC 21
#define TILE 256   // anchors per block in kernel 1

// ---------------- scratch (no allocations allowed) ----------------
__device__ float  g_ce[BB * AA];     // per-anchor cross entropy (4 MB)
__device__ int    g_numpos[BB];      // positives per image row
__device__ double g_loc;             // global smooth-L1 sum
__device__ double g_posce;           // global sum of ce over positive anchors
__device__ double g_clsneg[BB];      // per-row hard-negative ce sum

// ---------------- helpers ----------------
__device__ __forceinline__ unsigned tokey(float f) {
    unsigned u = __float_as_uint(f);
    // order-preserving map: float ascending <-> unsigned ascending
    return u ^ ((u & 0x80000000u) ? 0xFFFFFFFFu : 0x80000000u);
}
__device__ __forceinline__ float fromkey(unsigned k) {
    unsigned u = (k & 0x80000000u) ? (k ^ 0x80000000u) : ~k;
    return __uint_as_float(u);
}

__global__ void init_kernel() {
    int t = threadIdx.x;
    if (t < BB) { g_numpos[t] = 0; g_clsneg[t] = 0.0; }
    if (t == 0) { g_loc = 0.0; g_posce = 0.0; }
}

// ---------------- kernel 1: CE + loc loss, one streaming pass ----------------
__global__ void __launch_bounds__(TILE) ce_kernel(
    const float* __restrict__ loc_p, const float* __restrict__ loc_t,
    const float* __restrict__ cls_p, const int* __restrict__ cls_t)
{
    __shared__ float sh[TILE * CC];          // 21504 B, bank-conflict-free reads
    __shared__ int    s_cnt[8];
    __shared__ double s_loc[8], s_pce[8];

    const int b   = blockIdx.y;
    const int a0  = blockIdx.x * TILE;
    const int tid = threadIdx.x;

    // coalesced float4 staging of the 256x21 class-logit tile
    {
        const float4* src = (const float4*)(cls_p + (size_t)(b * AA + a0) * CC);
        float4* dst = (float4*)sh;
        const int n4 = TILE * CC / 4;        // 1344
        #pragma unroll
        for (int i = tid; i < n4; i += TILE) dst[i] = src[i];
    }
    __syncthreads();

    const int a  = a0 + tid;
    const int ct = cls_t[b * AA + a];
    const float* row = sh + tid * CC;        // stride 21 -> no bank conflicts

    float mx = row[0];
    #pragma unroll
    for (int c = 1; c < CC; ++c) mx = fmaxf(mx, row[c]);
    float s = 0.f;
    #pragma unroll
    for (int c = 0; c < CC; ++c) s += __expf(row[c] - mx);
    const int tgt = (ct < 0) ? 0 : ct;
    const float ce = mx + __logf(s) - row[tgt];
    g_ce[b * AA + a] = ce;

    const bool pos = (ct > 0);
    float locs = 0.f;
    if (pos) {
        float4 p = ((const float4*)loc_p)[b * AA + a];
        float4 t = ((const float4*)loc_t)[b * AA + a];
        float d;
        d = fabsf(p.x - t.x); locs += (d < 1.f) ? 0.5f * d * d : d - 0.5f;
        d = fabsf(p.y - t.y); locs += (d < 1.f) ? 0.5f * d * d : d - 0.5f;
        d = fabsf(p.z - t.z); locs += (d < 1.f) ? 0.5f * d * d : d - 0.5f;
        d = fabsf(p.w - t.w); locs += (d < 1.f) ? 0.5f * d * d : d - 0.5f;
    }

    // block reduce: count, loc sum, positive-ce sum (doubles for accuracy)
    int    cnt = pos ? 1 : 0;
    double dl  = (double)locs;
    double dp  = pos ? (double)ce : 0.0;
    #pragma unroll
    for (int o = 16; o; o >>= 1) {
        cnt += __shfl_down_sync(0xFFFFFFFFu, cnt, o);
        dl  += __shfl_down_sync(0xFFFFFFFFu, dl, o);
        dp  += __shfl_down_sync(0xFFFFFFFFu, dp, o);
    }
    const int w = tid >> 5, l = tid & 31;
    if (l == 0) { s_cnt[w] = cnt; s_loc[w] = dl; s_pce[w] = dp; }
    __syncthreads();
    if (w == 0) {
        int    c2 = (l < 8) ? s_cnt[l] : 0;
        double l2 = (l < 8) ? s_loc[l] : 0.0;
        double p2 = (l < 8) ? s_pce[l] : 0.0;
        #pragma unroll
        for (int o = 4; o; o >>= 1) {
            c2 += __shfl_down_sync(0xFFFFFFFFu, c2, o);
            l2 += __shfl_down_sync(0xFFFFFFFFu, l2, o);
            p2 += __shfl_down_sync(0xFFFFFFFFu, p2, o);
        }
        if (l == 0) {
            if (c2)        atomicAdd(&g_numpos[b], c2);
            if (l2 != 0.0) atomicAdd(&g_loc, l2);
            if (p2 != 0.0) atomicAdd(&g_posce, p2);
        }
    }
}

// ---------------- kernel 2: per-row radix select + top-k sum ----------------
__global__ void __launch_bounds__(1024) select_kernel() {
    const int b   = blockIdx.x;
    const int tid = threadIdx.x;
    const float* ce = g_ce + (size_t)b * AA;

    __shared__ unsigned hist[256];
    __shared__ unsigned sh_prefix, sh_mask, sh_krem;
    __shared__ double   sred[32];

    long long kk = 3LL * g_numpos[b];
    if (kk > AA) kk = AA;
    const unsigned k = (unsigned)kk;
    if (k == 0) { if (tid == 0) g_clsneg[b] = 0.0; return; }

    if (tid == 0) { sh_prefix = 0; sh_mask = 0; sh_krem = k; }
    __syncthreads();

    for (int s = 24; s >= 0; s -= 8) {
        if (tid < 256) hist[tid] = 0;
        __syncthreads();
        const unsigned pm = sh_mask, pv = sh_prefix;
        for (int i = tid; i < AA; i += 1024) {
            const unsigned key = tokey(ce[i]);
            if ((key & pm) == pv) {
                const unsigned d = (key >> s) & 0xFFu;
                // warp-aggregated atomic (CE exponents cluster -> few hot bins)
                const unsigned act   = __activemask();
                const unsigned peers = __match_any_sync(act, d);
                if ((tid & 31) == (unsigned)(__ffs(peers) - 1))
                    atomicAdd(&hist[d], (unsigned)__popc(peers));
            }
        }
        __syncthreads();
        if (tid == 0) {
            unsigned krem = sh_krem;
            int d = 255;
            for (; d > 0; --d) {
                const unsigned c = hist[d];
                if (c >= krem) break;
                krem -= c;
            }
            sh_prefix = pv | ((unsigned)d << s);
            sh_mask   = pm | (0xFFu << s);
            sh_krem   = krem;
        }
        __syncthreads();
    }

    const unsigned T    = sh_prefix;   // exact key of k-th largest ce
    const unsigned krem = sh_krem;     // how many ties at T are included

    double acc = 0.0;
    for (int i = tid; i < AA; i += 1024) {
        const float v = ce[i];
        if (tokey(v) > T) acc += (double)v;
    }
    #pragma unroll
    for (int o = 16; o; o >>= 1) acc += __shfl_down_sync(0xFFFFFFFFu, acc, o);
    if ((tid & 31) == 0) sred[tid >> 5] = acc;
    __syncthreads();
    if (tid < 32) {
        double v = sred[tid];
        #pragma unroll
        for (int o = 16; o; o >>= 1) v += __shfl_down_sync(0xFFFFFFFFu, v, o);
        if (tid == 0)
            g_clsneg[b] = v + (double)krem * (double)fromkey(T);
    }
}

// ---------------- kernel 3: combine ----------------
__global__ void final_kernel(float* __restrict__ out) {
    const int t = threadIdx.x;           // 32 threads
    double v = g_clsneg[t];
    int   np = g_numpos[t];
    #pragma unroll
    for (int o = 16; o; o >>= 1) {
        v  += __shfl_down_sync(0xFFFFFFFFu, v, o);
        np += __shfl_down_sync(0xFFFFFFFFu, np, o);
    }
    if (t == 0)
        out[0] = (float)((g_loc + g_posce + v) / (double)np);
}

// ---------------- launch ----------------
extern "C" void kernel_launch(void* const* d_in, const int* in_sizes, int n_in,
                              void* d_out, int out_size)
{
    const float* loc_p = (const float*)d_in[0];
    const float* loc_t = (const float*)d_in[1];
    const float* cls_p = (const float*)d_in[2];
    const int*   cls_t = (const int*)d_in[3];

    init_kernel<<<1, 32>>>();
    dim3 grid(AA / TILE, BB);
    ce_kernel<<<grid, TILE>>>(loc_p, loc_t, cls_p, cls_t);
    select_kernel<<<BB, 1024>>>();
    final_kernel<<<1, 32>>>((float*)d_out);
}

// round 2
// speedup vs baseline: 1.4614x; 1.4614x over previous
#include <cuda_runtime.h>
#include <cuda_bf16.h>

// Problem shape (fixed by the dataset)
#define BB 32
#define AA 32768
#define CC 21
#define TILE 256
#define HB 4096          // 2^12 bins: top 12 bits of order-preserving key
#define FULLM 0xFFFFFFFFu

// ---------------- scratch (zero-initialized BSS; each call leaves it zeroed) ----
__device__ float    g_ce[BB * AA];      // per-anchor CE (4 MB)
__device__ float    g_buf[BB * AA];     // boundary-bin compaction buffers
__device__ unsigned g_hist[BB * HB];    // per-row 12-bit count histogram
__device__ float    g_hsum[BB * HB];    // per-row 12-bit value-sum histogram
__device__ int      g_numpos[BB];
__device__ double   g_locr[BB];         // per-row smooth-L1 sum
__device__ double   g_pcer[BB];         // per-row positive-CE sum
__device__ double   g_fsum;
__device__ int      g_fnp;
__device__ int      g_ticket;

// ---------------- helpers ----------------
__device__ __forceinline__ unsigned tokey(float f) {
    unsigned u = __float_as_uint(f);
    return u ^ ((u & 0x80000000u) ? 0xFFFFFFFFu : 0x80000000u);  // order-preserving
}
__device__ __forceinline__ float fromkey(unsigned k) {
    unsigned u = (k & 0x80000000u) ? (k ^ 0x80000000u) : ~k;
    return __uint_as_float(u);
}

// inclusive suffix scan over 1024 block threads (value per thread)
__device__ __forceinline__ unsigned suffix_scan_block(unsigned v, int tid) {
    __shared__ unsigned s_wt[32];
    const int lane = tid & 31, w = tid >> 5;
    #pragma unroll
    for (int off = 1; off < 32; off <<= 1) {
        unsigned o = __shfl_down_sync(FULLM, v, off);
        if (lane + off < 32) v += o;
    }
    if (lane == 0) s_wt[w] = v;          // warp total
    __syncthreads();
    if (w == 0) {
        unsigned x = s_wt[lane], t2 = x;
        #pragma unroll
        for (int off = 1; off < 32; off <<= 1) {
            unsigned o = __shfl_down_sync(FULLM, t2, off);
            if (lane + off < 32) t2 += o;
        }
        s_wt[lane] = t2 - x;             // strict suffix of warp totals
    }
    __syncthreads();
    v += s_wt[w];
    __syncthreads();                     // protect s_wt reuse
    return v;
}

// block-wide double sum, broadcast to all threads
__device__ __forceinline__ double dsum_block(double v, int tid) {
    __shared__ double s_d[32];
    const int lane = tid & 31, w = tid >> 5;
    #pragma unroll
    for (int off = 16; off; off >>= 1) v += __shfl_down_sync(FULLM, v, off);
    if (lane == 0) s_d[w] = v;
    __syncthreads();
    if (w == 0) {
        double x = s_d[lane];
        #pragma unroll
        for (int off = 16; off; off >>= 1) x += __shfl_down_sync(FULLM, x, off);
        if (lane == 0) s_d[0] = x;
    }
    __syncthreads();
    double r = s_d[0];
    __syncthreads();                     // protect s_d reuse
    return r;
}

// ---------------- kernel 1: CE + loc loss + per-row histograms ----------------
__global__ void __launch_bounds__(TILE) ce_kernel(
    const float* __restrict__ loc_p, const float* __restrict__ loc_t,
    const float* __restrict__ cls_p, const int* __restrict__ cls_t)
{
    __shared__ float sh[TILE * CC];
    __shared__ int    s_cnt[8];
    __shared__ double s_loc[8], s_pce[8];

    const int b   = blockIdx.y;
    const int a0  = blockIdx.x * TILE;
    const int tid = threadIdx.x;

    {   // coalesced float4 staging of 256x21 logits
        const float4* src = (const float4*)(cls_p + (size_t)(b * AA + a0) * CC);
        float4* dst = (float4*)sh;
        const int n4 = TILE * CC / 4;
        #pragma unroll
        for (int i = tid; i < n4; i += TILE) dst[i] = src[i];
    }
    __syncthreads();

    const int a  = a0 + tid;
    const int ct = cls_t[b * AA + a];
    const float* row = sh + tid * CC;    // stride 21 -> conflict-free

    float mx = row[0];
    #pragma unroll
    for (int c = 1; c < CC; ++c) mx = fmaxf(mx, row[c]);
    float s = 0.f;
    #pragma unroll
    for (int c = 0; c < CC; ++c) s += __expf(row[c] - mx);
    const int tgt = (ct < 0) ? 0 : ct;
    const float ce = mx + __logf(s) - row[tgt];
    g_ce[b * AA + a] = ce;

    // per-row 12-bit histograms (warp-aggregated count, per-lane sum)
    {
        const unsigned key = tokey(ce);
        const unsigned dg  = key >> 20;
        const unsigned peers = __match_any_sync(FULLM, dg);
        if ((tid & 31) == (unsigned)(__ffs(peers) - 1))
            atomicAdd(&g_hist[b * HB + dg], (unsigned)__popc(peers));
        atomicAdd(&g_hsum[b * HB + dg], ce);
    }

    const bool pos = (ct > 0);
    float locs = 0.f;
    if (pos) {
        float4 p = ((const float4*)loc_p)[b * AA + a];
        float4 t = ((const float4*)loc_t)[b * AA + a];
        float d;
        d = fabsf(p.x - t.x); locs += (d < 1.f) ? 0.5f * d * d : d - 0.5f;
        d = fabsf(p.y - t.y); locs += (d < 1.f) ? 0.5f * d * d : d - 0.5f;
        d = fabsf(p.z - t.z); locs += (d < 1.f) ? 0.5f * d * d : d - 0.5f;
        d = fabsf(p.w - t.w); locs += (d < 1.f) ? 0.5f * d * d : d - 0.5f;
    }

    int    cnt = pos ? 1 : 0;
    double dl  = (double)locs;
    double dp  = pos ? (double)ce : 0.0;
    #pragma unroll
    for (int o = 16; o; o >>= 1) {
        cnt += __shfl_down_sync(FULLM, cnt, o);
        dl  += __shfl_down_sync(FULLM, dl, o);
        dp  += __shfl_down_sync(FULLM, dp, o);
    }
    const int w = tid >> 5, l = tid & 31;
    if (l == 0) { s_cnt[w] = cnt; s_loc[w] = dl; s_pce[w] = dp; }
    __syncthreads();
    if (w == 0) {
        int    c2 = (l < 8) ? s_cnt[l] : 0;
        double l2 = (l < 8) ? s_loc[l] : 0.0;
        double p2 = (l < 8) ? s_pce[l] : 0.0;
        #pragma unroll
        for (int o = 4; o; o >>= 1) {
            c2 += __shfl_down_sync(FULLM, c2, o);
            l2 += __shfl_down_sync(FULLM, l2, o);
            p2 += __shfl_down_sync(FULLM, p2, o);
        }
        if (l == 0) {   // per-row addresses: no cross-row serialization
            if (c2)        atomicAdd(&g_numpos[b], c2);
            if (l2 != 0.0) atomicAdd(&g_locr[b], l2);
            if (p2 != 0.0) atomicAdd(&g_pcer[b], p2);
        }
    }
}

// ---------------- kernel 2: hist-driven top-k sum + combine + state reset ------
__global__ void __launch_bounds__(1024) select_kernel(float* __restrict__ out)
{
    const int b = blockIdx.x, tid = threadIdx.x;
    const unsigned lane = tid & 31;

    __shared__ unsigned s_hist[1024];
    __shared__ float    s_hs[1024];
    __shared__ unsigned s_d0, s_krem, s_cbin, s_cnt;
    __shared__ unsigned s_dA, s_kA, s_dB, s_kB;

    const int np = g_numpos[b];
    long long kk = 3LL * np; if (kk > AA) kk = AA;
    const unsigned k = (unsigned)kk;

    double sum_above = 0.0, sum_in = 0.0;

    if (k > 0) {
        // ---- level 0: 12-bit pre-histogram (4 bins/thread) ----
        const int base = b * HB + tid * 4;
        const uint4 cv = *(const uint4*)(g_hist + base);
        unsigned cc4[4] = {cv.x, cv.y, cv.z, cv.w};
        const unsigned tot = cc4[0] + cc4[1] + cc4[2] + cc4[3];
        const unsigned A = suffix_scan_block(tot, tid);
        unsigned ab = A - tot;                    // count strictly above my bins
        #pragma unroll
        for (int j = 3; j >= 0; --j) {            // walk high->low bin
            if (ab < k && k <= ab + cc4[j]) {
                s_d0 = (unsigned)(tid * 4 + j); s_krem = k - ab; s_cbin = cc4[j];
            }
            ab += cc4[j];
        }
        __syncthreads();
        const unsigned d0 = s_d0, krem = s_krem, cbin = s_cbin;

        // exact sum of all full bins above the boundary bin
        const float4 hv = *(const float4*)(g_hsum + base);
        double la = 0.0;
        const unsigned bi = (unsigned)(tid * 4);
        if (bi + 0 > d0) la += (double)hv.x;
        if (bi + 1 > d0) la += (double)hv.y;
        if (bi + 2 > d0) la += (double)hv.z;
        if (bi + 3 > d0) la += (double)hv.w;
        sum_above = dsum_block(la, tid);

        if (krem == cbin) {
            sum_in = (double)g_hsum[b * HB + d0];  // whole bin included, no row read
        } else {
            // ---- compact boundary-bin elements (the only full row read) ----
            if (tid == 0) s_cnt = 0u;
            __syncthreads();
            const float4* row4 = (const float4*)(g_ce + (size_t)b * AA);
            float* buf = g_buf + (size_t)b * AA;
            #pragma unroll
            for (int it = 0; it < 8; ++it) {
                const float4 v = row4[tid + it * 1024];
                const float xs[4] = {v.x, v.y, v.z, v.w};
                #pragma unroll
                for (int e = 0; e < 4; ++e) {
                    const float x = xs[e];
                    const bool p = ((tokey(x) >> 20) == d0);
                    const unsigned m = __ballot_sync(FULLM, p);
                    if (m) {
                        const int ldr = __ffs(m) - 1;
                        unsigned bp = 0;
                        if ((int)lane == ldr) bp = atomicAdd(&s_cnt, (unsigned)__popc(m));
                        bp = __shfl_sync(FULLM, bp, ldr);
                        if (p) buf[bp + __popc(m & ((1u << lane) - 1u))] = x;
                    }
                }
            }
            __syncthreads();
            const unsigned cn = s_cnt;

            // ---- level 1: bits 19:10 over candidates ----
            s_hist[tid] = 0u; s_hs[tid] = 0.f;
            __syncthreads();
            for (unsigned i = tid; i < cn; i += 1024) {
                const float x = buf[i];
                const unsigned dA = (tokey(x) >> 10) & 1023u;
                const unsigned act = __activemask();
                const unsigned peers = __match_any_sync(act, dA);
                if (lane == (unsigned)(__ffs(peers) - 1))
                    atomicAdd(&s_hist[dA], (unsigned)__popc(peers));
                atomicAdd(&s_hs[dA], x);
            }
            __syncthreads();
            {
                const unsigned cA = s_hist[tid];
                const unsigned A2 = suffix_scan_block(cA, tid);
                const unsigned strict = A2 - cA;
                if (strict < krem && krem <= A2) { s_dA = tid; s_kA = krem - strict; }
            }
            __syncthreads();
            const unsigned dA0 = s_dA, kA = s_kA;
            const unsigned cA0 = s_hist[dA0];
            const float    hsA0 = s_hs[dA0];
            double la2 = (tid > (int)dA0) ? (double)s_hs[tid] : 0.0;
            const double sumA_above = dsum_block(la2, tid);

            if (kA == cA0) {
                sum_in = sumA_above + (double)hsA0;
            } else {
                // ---- level 2: bits 9:0 ----
                s_hist[tid] = 0u; s_hs[tid] = 0.f;
                __syncthreads();
                for (unsigned i = tid; i < cn; i += 1024) {
                    const float x = buf[i];
                    const unsigned key = tokey(x);
                    if (((key >> 10) & 1023u) == dA0) {
                        const unsigned dB = key & 1023u;
                        const unsigned act = __activemask();
                        const unsigned peers = __match_any_sync(act, dB);
                        if (lane == (unsigned)(__ffs(peers) - 1))
                            atomicAdd(&s_hist[dB], (unsigned)__popc(peers));
                        atomicAdd(&s_hs[dB], x);
                    }
                }
                __syncthreads();
                {
                    const unsigned cB = s_hist[tid];
                    const unsigned AB = suffix_scan_block(cB, tid);
                    const unsigned strictB = AB - cB;
                    if (strictB < kA && kA <= AB) { s_dB = tid; s_kB = kA - strictB; }
                }
                __syncthreads();
                const unsigned dB0 = s_dB, kB = s_kB;
                double lb = (tid > (int)dB0) ? (double)s_hs[tid] : 0.0;
                const double sumB_above = dsum_block(lb, tid);
                const unsigned Tkey = (d0 << 20) | (dA0 << 10) | dB0;
                sum_in = sumA_above + sumB_above + (double)kB * (double)fromkey(Tkey);
            }
        }
    }

    // reset this row's histograms for the next replay
    {
        const int base = b * HB + tid * 4;
        *(uint4*)(g_hist + base)  = make_uint4(0u, 0u, 0u, 0u);
        *(float4*)(g_hsum + base) = make_float4(0.f, 0.f, 0.f, 0.f);
    }

    if (tid == 0) {
        const double part = sum_above + sum_in + g_locr[b] + g_pcer[b];
        atomicAdd(&g_fsum, part);
        atomicAdd(&g_fnp, np);
        g_locr[b] = 0.0; g_pcer[b] = 0.0; g_numpos[b] = 0;
        __threadfence();
        const int tk = atomicAdd(&g_ticket, 1);
        if (tk == BB - 1) {               // last finisher combines + resets scalars
            const double fs = atomicAdd(&g_fsum, 0.0);
            const int    fn = atomicAdd(&g_fnp, 0);
            out[0] = (float)(fs / (double)fn);
            g_fsum = 0.0; g_fnp = 0; g_ticket = 0;
            __threadfence();
        }
    }
}

// ---------------- launch (2 kernels) ----------------
extern "C" void kernel_launch(void* const* d_in, const int* in_sizes, int n_in,
                              void* d_out, int out_size)
{
    const float* loc_p = (const float*)d_in[0];
    const float* loc_t = (const float*)d_in[1];
    const float* cls_p = (const float*)d_in[2];
    const int*   cls_t = (const int*)d_in[3];

    dim3 grid(AA / TILE, BB);
    ce_kernel<<<grid, TILE>>>(loc_p, loc_t, cls_p, cls_t);
    select_kernel<<<BB, 1024>>>((float*)d_out);
}

// round 4
// speedup vs baseline: 2.2590x; 1.5457x over previous
#include <cuda_runtime.h>
#include <cuda_bf16.h>

// Problem shape (fixed by the dataset)
#define BB 32
#define AA 32768
#define CC 21
#define TILE 256
#define HB 4096          // 2^12 bins: top 12 bits of order-preserving key
#define FULLM 0xFFFFFFFFu

// ---------------- scratch (zero-initialized BSS; each call leaves it zeroed) ----
__device__ float    g_ce[BB * AA];      // per-anchor CE (4 MB, L2-resident)
__device__ unsigned g_hist[BB * HB];    // per-row 12-bit count histogram
__device__ int      g_numpos[BB];
__device__ double   g_locr[BB];         // per-row smooth-L1 sum
__device__ double   g_pcer[BB];         // per-row positive-CE sum
__device__ double   g_fsum;
__device__ int      g_fnp;
__device__ int      g_ticket;

// ---------------- helpers ----------------
__device__ __forceinline__ unsigned tokey(float f) {
    unsigned u = __float_as_uint(f);
    return u ^ ((u & 0x80000000u) ? 0xFFFFFFFFu : 0x80000000u);  // order-preserving
}
__device__ __forceinline__ float fromkey(unsigned k) {
    unsigned u = (k & 0x80000000u) ? (k ^ 0x80000000u) : ~k;
    return __uint_as_float(u);
}

// inclusive suffix scan over 1024 block threads
__device__ __forceinline__ unsigned suffix_scan_block(unsigned v, int tid) {
    __shared__ unsigned s_wt[32];
    const int lane = tid & 31, w = tid >> 5;
    #pragma unroll
    for (int off = 1; off < 32; off <<= 1) {
        unsigned o = __shfl_down_sync(FULLM, v, off);
        if (lane + off < 32) v += o;
    }
    if (lane == 0) s_wt[w] = v;
    __syncthreads();
    if (w == 0) {
        unsigned x = s_wt[lane], t2 = x;
        #pragma unroll
        for (int off = 1; off < 32; off <<= 1) {
            unsigned o = __shfl_down_sync(FULLM, t2, off);
            if (lane + off < 32) t2 += o;
        }
        s_wt[lane] = t2 - x;             // strict suffix of warp totals
    }
    __syncthreads();
    v += s_wt[w];
    __syncthreads();
    return v;
}

// ---------------- kernel 1: CE + loc loss + per-row count histogram ------------
__global__ void __launch_bounds__(TILE) ce_kernel(
    const float* __restrict__ loc_p, const float* __restrict__ loc_t,
    const float* __restrict__ cls_p, const int* __restrict__ cls_t)
{
    __shared__ float sh[TILE * CC];
    __shared__ int    s_cnt[8];
    __shared__ double s_loc[8], s_pce[8];

    const int b   = blockIdx.y;
    const int a0  = blockIdx.x * TILE;
    const int tid = threadIdx.x;

    {   // coalesced float4 staging of 256x21 logits
        const float4* src = (const float4*)(cls_p + (size_t)(b * AA + a0) * CC);
        float4* dst = (float4*)sh;
        const int n4 = TILE * CC / 4;
        #pragma unroll
        for (int i = tid; i < n4; i += TILE) dst[i] = src[i];
    }
    __syncthreads();

    const int a  = a0 + tid;
    const int ct = cls_t[b * AA + a];
    const float* row = sh + tid * CC;    // stride 21 -> conflict-free

    float mx = row[0];
    #pragma unroll
    for (int c = 1; c < CC; ++c) mx = fmaxf(mx, row[c]);
    float s = 0.f;
    #pragma unroll
    for (int c = 0; c < CC; ++c) s += __expf(row[c] - mx);
    const int tgt = (ct < 0) ? 0 : ct;
    const float ce = mx + __logf(s) - row[tgt];
    g_ce[b * AA + a] = ce;

    // per-row 12-bit COUNT histogram (warp-aggregated: one RED per bin per warp)
    {
        const unsigned dg    = tokey(ce) >> 20;
        const unsigned peers = __match_any_sync(FULLM, dg);
        if ((tid & 31) == (unsigned)(__ffs(peers) - 1))
            atomicAdd(&g_hist[b * HB + dg], (unsigned)__popc(peers));
    }

    const bool pos = (ct > 0);
    float locs = 0.f;
    if (pos) {
        float4 p = ((const float4*)loc_p)[b * AA + a];
        float4 t = ((const float4*)loc_t)[b * AA + a];
        float d;
        d = fabsf(p.x - t.x); locs += (d < 1.f) ? 0.5f * d * d : d - 0.5f;
        d = fabsf(p.y - t.y); locs += (d < 1.f) ? 0.5f * d * d : d - 0.5f;
        d = fabsf(p.z - t.z); locs += (d < 1.f) ? 0.5f * d * d : d - 0.5f;
        d = fabsf(p.w - t.w); locs += (d < 1.f) ? 0.5f * d * d : d - 0.5f;
    }

    int    cnt = pos ? 1 : 0;
    double dl  = (double)locs;
    double dp  = pos ? (double)ce : 0.0;
    #pragma unroll
    for (int o = 16; o; o >>= 1) {
        cnt += __shfl_down_sync(FULLM, cnt, o);
        dl  += __shfl_down_sync(FULLM, dl, o);
        dp  += __shfl_down_sync(FULLM, dp, o);
    }
    const int w = tid >> 5, l = tid & 31;
    if (l == 0) { s_cnt[w] = cnt; s_loc[w] = dl; s_pce[w] = dp; }
    __syncthreads();
    if (w == 0) {
        int    c2 = (l < 8) ? s_cnt[l] : 0;
        double l2 = (l < 8) ? s_loc[l] : 0.0;
        double p2 = (l < 8) ? s_pce[l] : 0.0;
        #pragma unroll
        for (int o = 4; o; o >>= 1) {
            c2 += __shfl_down_sync(FULLM, c2, o);
            l2 += __shfl_down_sync(FULLM, l2, o);
            p2 += __shfl_down_sync(FULLM, p2, o);
        }
        if (l == 0) {   // per-row addresses: 128 contenders each, cheap
            if (c2)        atomicAdd(&g_numpos[b], c2);
            if (l2 != 0.0) atomicAdd(&g_locr[b], l2);
            if (p2 != 0.0) atomicAdd(&g_pcer[b], p2);
        }
    }
}

// ---- count-only shared histogram pass over the CE row, with predicate --------
// mode 0: digit = bits 19:10 of keys whose top-12 == sel
// mode 1: digit = bits  9:0 of keys whose top-22 == sel
__device__ __forceinline__ void hist_pass(
    const float4* __restrict__ row4, unsigned* s_hist, int tid,
    int mode, unsigned sel)
{
    const unsigned lane = tid & 31;
    s_hist[tid] = 0u;
    __syncthreads();
    #pragma unroll
    for (int it = 0; it < 8; ++it) {
        const float4 v = row4[tid + it * 1024];
        const float xs[4] = {v.x, v.y, v.z, v.w};
        #pragma unroll
        for (int e = 0; e < 4; ++e) {
            const unsigned key = tokey(xs[e]);
            const bool p = (mode == 0) ? ((key >> 20) == sel)
                                       : ((key >> 10) == sel);
            if (p) {
                const unsigned d = (mode == 0) ? ((key >> 10) & 1023u)
                                               : (key & 1023u);
                const unsigned act   = __activemask();
                const unsigned peers = __match_any_sync(act, d);
                if (lane == (unsigned)(__ffs(peers) - 1))
                    atomicAdd(&s_hist[d], (unsigned)__popc(peers));
            }
        }
    }
    __syncthreads();
}

// ---------------- kernel 2: hist-driven top-k sum + combine + state reset ------
__global__ void __launch_bounds__(1024) select_kernel(float* __restrict__ out)
{
    const int b = blockIdx.x, tid = threadIdx.x;

    __shared__ unsigned s_hist[1024];
    __shared__ unsigned s_d0, s_krem, s_cbin;
    __shared__ unsigned s_dx, s_kx;
    __shared__ double   s_red[32];

    const int np = g_numpos[b];
    long long kk = 3LL * np; if (kk > AA) kk = AA;
    const unsigned k = (unsigned)kk;
    const float4* row4 = (const float4*)(g_ce + (size_t)b * AA);

    double result = 0.0;

    if (k > 0) {
        // ---- level 0: 12-bit pre-histogram (4 bins/thread) ----
        const int base = b * HB + tid * 4;
        const uint4 cv = *(const uint4*)(g_hist + base);
        const unsigned cc4[4] = {cv.x, cv.y, cv.z, cv.w};
        const unsigned tot = cc4[0] + cc4[1] + cc4[2] + cc4[3];
        const unsigned A = suffix_scan_block(tot, tid);
        unsigned ab = A - tot;                     // strictly above my 4 bins
        #pragma unroll
        for (int j = 3; j >= 0; --j) {             // walk high->low
            if (ab < k && k <= ab + cc4[j]) {
                s_d0 = (unsigned)(tid * 4 + j); s_krem = k - ab; s_cbin = cc4[j];
            }
            ab += cc4[j];
        }
        __syncthreads();
        const unsigned d0 = s_d0, krem = s_krem, cbin = s_cbin;

        unsigned Bound;         // select all elements with key >= Bound ...
        double   extra = 0.0;   // ... plus this tie contribution (added ONCE)

        if (krem == cbin) {
            Bound = d0 << 20;
        } else {
            // ---- level 1: bits 19:10 within bin d0 ----
            hist_pass(row4, s_hist, tid, 0, d0);
            {
                const unsigned c = s_hist[tid];
                const unsigned A2 = suffix_scan_block(c, tid);
                if (A2 - c < krem && krem <= A2) { s_dx = (unsigned)tid; s_kx = krem - (A2 - c); }
            }
            __syncthreads();
            const unsigned dA0 = s_dx, kA = s_kx, cA0 = s_hist[dA0];
            __syncthreads();

            if (kA == cA0) {
                Bound = (d0 << 20) | (dA0 << 10);
            } else {
                // ---- level 2: bits 9:0 within (d0, dA0) ----
                hist_pass(row4, s_hist, tid, 1, (d0 << 10) | dA0);
                {
                    const unsigned c = s_hist[tid];
                    const unsigned A3 = suffix_scan_block(c, tid);
                    if (A3 - c < kA && kA <= A3) { s_dx = (unsigned)tid; s_kx = kA - (A3 - c); }
                }
                __syncthreads();
                const unsigned T = (d0 << 20) | (dA0 << 10) | s_dx;
                extra = (double)s_kx * (double)fromkey(T);
                Bound = T + 1u;
            }
        }

        // ---- final pass: exact sum of all selected elements ----
        // BUGFIX (R3): seed the tie term on thread 0 only, not all 1024 threads.
        double acc = (tid == 0) ? extra : 0.0;
        #pragma unroll
        for (int it = 0; it < 8; ++it) {
            const float4 v = row4[tid + it * 1024];
            if (tokey(v.x) >= Bound) acc += (double)v.x;
            if (tokey(v.y) >= Bound) acc += (double)v.y;
            if (tokey(v.z) >= Bound) acc += (double)v.z;
            if (tokey(v.w) >= Bound) acc += (double)v.w;
        }
        #pragma unroll
        for (int o = 16; o; o >>= 1) acc += __shfl_down_sync(FULLM, acc, o);
        if ((tid & 31) == 0) s_red[tid >> 5] = acc;
        __syncthreads();
        if (tid < 32) {
            double v = s_red[tid];
            #pragma unroll
            for (int o = 16; o; o >>= 1) v += __shfl_down_sync(FULLM, v, o);
            if (tid == 0) result = v;
        }
    }

    // reset this row's histogram for the next graph replay
    {
        const int base = b * HB + tid * 4;
        *(uint4*)(g_hist + base) = make_uint4(0u, 0u, 0u, 0u);
    }

    if (tid == 0) {
        const double part = result + g_locr[b] + g_pcer[b];
        atomicAdd(&g_fsum, part);
        atomicAdd(&g_fnp, np);
        g_locr[b] = 0.0; g_pcer[b] = 0.0; g_numpos[b] = 0;
        __threadfence();
        const int tk = atomicAdd(&g_ticket, 1);
        if (tk == BB - 1) {               // last finisher: combine + reset scalars
            const double fs = atomicAdd(&g_fsum, 0.0);
            const int    fn = atomicAdd(&g_fnp, 0);
            out[0] = (float)(fs / (double)fn);
            g_fsum = 0.0; g_fnp = 0; g_ticket = 0;
            __threadfence();
        }
    }
}

// ---------------- launch (2 kernels) ----------------
extern "C" void kernel_launch(void* const* d_in, const int* in_sizes, int n_in,
                              void* d_out, int out_size)
{
    const float* loc_p = (const float*)d_in[0];
    const float* loc_t = (const float*)d_in[1];
    const float* cls_p = (const float*)d_in[2];
    const int*   cls_t = (const int*)d_in[3];

    dim3 grid(AA / TILE, BB);
    ce_kernel<<<grid, TILE>>>(loc_p, loc_t, cls_p, cls_t);
    select_kernel<<<BB, 1024>>>((float*)d_out);
}

// round 5
// speedup vs baseline: 2.4883x; 1.1015x over previous
#include <cuda_runtime.h>
#include <cuda_bf16.h>

// Problem shape (fixed by the dataset)
#define BB 32
#define AA 32768
#define CC 21
#define TILE 256
#define HB 4096          // 2^12 bins
#define NSPLIT 4         // blocks per row in select (128 total <= 148 SMs: co-resident)
#define SEGV4 (AA / NSPLIT / 4)   // 2048 float4 per segment
#define FULLM 0xFFFFFFFFu

// ---------------- scratch (zero-initialized BSS; left zeroed after each call) --
__device__ float    g_ce[BB * AA];      // per-anchor CE (4 MB, L2-resident)
__device__ unsigned g_hist[BB * HB];    // per-row hist of key bits 31:20
__device__ unsigned g_hist2[BB * HB];   // per-row refine hist of key bits 19:8
__device__ int      g_numpos[BB];
__device__ double   g_locr[BB];
__device__ double   g_pcer[BB];
__device__ double   g_rowsum[BB];
__device__ int      g_arr1[BB];
__device__ int      g_arr2[BB];
__device__ double   g_fsum;
__device__ int      g_fnp;
__device__ int      g_ticket;

// ---------------- helpers ----------------
__device__ __forceinline__ unsigned tokey(float f) {
    unsigned u = __float_as_uint(f);
    return u ^ ((u & 0x80000000u) ? 0xFFFFFFFFu : 0x80000000u);  // order-preserving
}
__device__ __forceinline__ float fromkey(unsigned k) {
    unsigned u = (k & 0x80000000u) ? (k ^ 0x80000000u) : ~k;
    return __uint_as_float(u);
}

// inclusive suffix scan over 1024 block threads
__device__ __forceinline__ unsigned suffix_scan_block(unsigned v, int tid) {
    __shared__ unsigned s_wt[32];
    const int lane = tid & 31, w = tid >> 5;
    #pragma unroll
    for (int off = 1; off < 32; off <<= 1) {
        unsigned o = __shfl_down_sync(FULLM, v, off);
        if (lane + off < 32) v += o;
    }
    if (lane == 0) s_wt[w] = v;
    __syncthreads();
    if (w == 0) {
        unsigned x = s_wt[lane], t2 = x;
        #pragma unroll
        for (int off = 1; off < 32; off <<= 1) {
            unsigned o = __shfl_down_sync(FULLM, t2, off);
            if (lane + off < 32) t2 += o;
        }
        s_wt[lane] = t2 - x;             // strict suffix of warp totals
    }
    __syncthreads();
    v += s_wt[w];
    __syncthreads();
    return v;
}

// bracket the target kt inside 4096 bins held 4/thread (desc order = high bin first)
// writes (bin, remaining) to s_dx/s_kx. Exactly one thread matches.
__device__ __forceinline__ void bracket4(const unsigned c4[4], unsigned kt, int tid,
                                         unsigned* s_dx, unsigned* s_kx) {
    const unsigned tot = c4[0] + c4[1] + c4[2] + c4[3];
    const unsigned A = suffix_scan_block(tot, tid);
    unsigned ab = A - tot;               // count strictly above my 4 bins
    #pragma unroll
    for (int j = 3; j >= 0; --j) {       // high bin -> low bin
        if (ab < kt && kt <= ab + c4[j]) { *s_dx = (unsigned)(tid * 4 + j); *s_kx = kt - ab; }
        ab += c4[j];
    }
    __syncthreads();
}

// ---------------- kernel 1: CE + loc loss + per-row count histogram ------------
__global__ void __launch_bounds__(TILE) ce_kernel(
    const float* __restrict__ loc_p, const float* __restrict__ loc_t,
    const float* __restrict__ cls_p, const int* __restrict__ cls_t)
{
    __shared__ float sh[TILE * CC];
    __shared__ int    s_cnt[8];
    __shared__ double s_loc[8], s_pce[8];

    const int b   = blockIdx.y;
    const int a0  = blockIdx.x * TILE;
    const int tid = threadIdx.x;

    {   // coalesced float4 staging of 256x21 logits
        const float4* src = (const float4*)(cls_p + (size_t)(b * AA + a0) * CC);
        float4* dst = (float4*)sh;
        const int n4 = TILE * CC / 4;
        #pragma unroll
        for (int i = tid; i < n4; i += TILE) dst[i] = src[i];
    }
    __syncthreads();

    const int a  = a0 + tid;
    const int ct = cls_t[b * AA + a];
    const float* row = sh + tid * CC;    // stride 21 -> conflict-free

    float mx = row[0];
    #pragma unroll
    for (int c = 1; c < CC; ++c) mx = fmaxf(mx, row[c]);
    float s = 0.f;
    #pragma unroll
    for (int c = 0; c < CC; ++c) s += __expf(row[c] - mx);
    const int tgt = (ct < 0) ? 0 : ct;
    const float ce = mx + __logf(s) - row[tgt];
    g_ce[b * AA + a] = ce;

    {   // warp-aggregated count histogram (key bits 31:20)
        const unsigned dg    = tokey(ce) >> 20;
        const unsigned peers = __match_any_sync(FULLM, dg);
        if ((tid & 31) == (unsigned)(__ffs(peers) - 1))
            atomicAdd(&g_hist[b * HB + dg], (unsigned)__popc(peers));
    }

    const bool pos = (ct > 0);
    float locs = 0.f;
    if (pos) {
        float4 p = ((const float4*)loc_p)[b * AA + a];
        float4 t = ((const float4*)loc_t)[b * AA + a];
        float d;
        d = fabsf(p.x - t.x); locs += (d < 1.f) ? 0.5f * d * d : d - 0.5f;
        d = fabsf(p.y - t.y); locs += (d < 1.f) ? 0.5f * d * d : d - 0.5f;
        d = fabsf(p.z - t.z); locs += (d < 1.f) ? 0.5f * d * d : d - 0.5f;
        d = fabsf(p.w - t.w); locs += (d < 1.f) ? 0.5f * d * d : d - 0.5f;
    }

    int    cnt = pos ? 1 : 0;
    double dl  = (double)locs;
    double dp  = pos ? (double)ce : 0.0;
    #pragma unroll
    for (int o = 16; o; o >>= 1) {
        cnt += __shfl_down_sync(FULLM, cnt, o);
        dl  += __shfl_down_sync(FULLM, dl, o);
        dp  += __shfl_down_sync(FULLM, dp, o);
    }
    const int w = tid >> 5, l = tid & 31;
    if (l == 0) { s_cnt[w] = cnt; s_loc[w] = dl; s_pce[w] = dp; }
    __syncthreads();
    if (w == 0) {
        int    c2 = (l < 8) ? s_cnt[l] : 0;
        double l2 = (l < 8) ? s_loc[l] : 0.0;
        double p2 = (l < 8) ? s_pce[l] : 0.0;
        #pragma unroll
        for (int o = 4; o; o >>= 1) {
            c2 += __shfl_down_sync(FULLM, c2, o);
            l2 += __shfl_down_sync(FULLM, l2, o);
            p2 += __shfl_down_sync(FULLM, p2, o);
        }
        if (l == 0) {
            if (c2)        atomicAdd(&g_numpos[b], c2);
            if (l2 != 0.0) atomicAdd(&g_locr[b], l2);
            if (p2 != 0.0) atomicAdd(&g_pcer[b], p2);
        }
    }
}

// ---------------- kernel 2: NSPLIT blocks per row cooperate ----------------
__global__ void __launch_bounds__(1024) select_kernel(float* __restrict__ out)
{
    const int b = blockIdx.y, sp = blockIdx.x, tid = threadIdx.x;
    const unsigned lane = tid & 31;

    __shared__ unsigned s_hist[HB];     // 16 KB
    __shared__ unsigned s_d0, s_krem, s_cbin, s_dx, s_kx;
    __shared__ double   s_red[32];
    __shared__ int      s_last;

    const int np = g_numpos[b];
    long long kk = 3LL * np; if (kk > AA) kk = AA;
    const unsigned k = (unsigned)kk;

    const float4* row4  = (const float4*)(g_ce + (size_t)b * AA);
    const int     segv4 = sp * SEGV4;
    const int     hbase = b * HB + tid * 4;

    unsigned long long Bound = 0xFFFFFFFFFFFFFFFFull;  // select none (k==0)
    double tie = 0.0;

    if (k > 0) {
        // ---- level 0: bracket k in the prebuilt 12-bit histogram ----
        {
            const uint4 cv = *(const uint4*)(g_hist + hbase);
            const unsigned c4[4] = {cv.x, cv.y, cv.z, cv.w};
            bracket4(c4, k, tid, &s_d0, &s_krem);
            if ((unsigned)(tid * 4) <= s_d0 && s_d0 < (unsigned)(tid * 4 + 4))
                s_cbin = c4[s_d0 & 3u];
        }
        __syncthreads();
        const unsigned d0 = s_d0, krem = s_krem, cbin = s_cbin;

        if (krem == cbin) {
            Bound = ((unsigned long long)d0) << 20;     // whole bin: exact
        } else {
            // ---- phase 1: this block's segment -> smem hist of bits 19:8 ----
            *(uint4*)(s_hist + tid * 4) = make_uint4(0u, 0u, 0u, 0u);
            __syncthreads();
            #pragma unroll
            for (int it = 0; it < SEGV4 / 1024; ++it) {
                const float4 v = row4[segv4 + tid + it * 1024];
                const float xs[4] = {v.x, v.y, v.z, v.w};
                #pragma unroll
                for (int e = 0; e < 4; ++e) {
                    const unsigned key = tokey(xs[e]);
                    if ((key >> 20) == d0) {
                        const unsigned d = (key >> 8) & 4095u;
                        const unsigned act   = __activemask();
                        const unsigned peers = __match_any_sync(act, d);
                        if (lane == (unsigned)(__ffs(peers) - 1))
                            atomicAdd(&s_hist[d], (unsigned)__popc(peers));
                    }
                }
            }
            __syncthreads();
            // sparse flush to the row's global refine histogram
            #pragma unroll
            for (int j = 0; j < 4; ++j) {
                const unsigned c = s_hist[tid * 4 + j];
                if (c) atomicAdd(&g_hist2[hbase + j], c);
            }
            __syncthreads();
            if (tid == 0) {
                __threadfence();
                atomicAdd(&g_arr1[b], 1);
                while (atomicAdd(&g_arr1[b], 0) < NSPLIT) { }
            }
            __syncthreads();
            // ---- all row blocks identically bracket krem in g_hist2 ----
            {
                unsigned c4[4];
                #pragma unroll
                for (int j = 0; j < 4; ++j) c4[j] = __ldcg(&g_hist2[hbase + j]);
                bracket4(c4, krem, tid, &s_dx, &s_kx);
            }
            const unsigned d1 = s_dx, k2 = s_kx;
            const unsigned base24 = (d0 << 20) | (d1 << 8);
            // ties approximated at bin base: rel error <= 2^-15 per tie element
            tie   = (double)k2 * (double)fromkey(base24);
            Bound = (unsigned long long)base24 + 256ull;
        }
    }

    // ---- phase 2: segment sum of selected elements ----
    double acc = 0.0;
    if (k > 0) {
        #pragma unroll
        for (int it = 0; it < SEGV4 / 1024; ++it) {
            const float4 v = row4[segv4 + tid + it * 1024];
            if ((unsigned long long)tokey(v.x) >= Bound) acc += (double)v.x;
            if ((unsigned long long)tokey(v.y) >= Bound) acc += (double)v.y;
            if ((unsigned long long)tokey(v.z) >= Bound) acc += (double)v.z;
            if ((unsigned long long)tokey(v.w) >= Bound) acc += (double)v.w;
        }
    }
    #pragma unroll
    for (int o = 16; o; o >>= 1) acc += __shfl_down_sync(FULLM, acc, o);
    if (lane == 0) s_red[tid >> 5] = acc;
    __syncthreads();
    if (tid < 32) {
        double v = s_red[tid];
        #pragma unroll
        for (int o = 16; o; o >>= 1) v += __shfl_down_sync(FULLM, v, o);
        if (tid == 0 && k > 0 && v != 0.0) atomicAdd(&g_rowsum[b], v);
    }
    __syncthreads();
    if (tid == 0) {
        __threadfence();
        s_last = (atomicAdd(&g_arr2[b], 1) == NSPLIT - 1);
    }
    __syncthreads();

    if (s_last) {       // last block of this row: combine + reset row state
        *(uint4*)(g_hist + hbase)  = make_uint4(0u, 0u, 0u, 0u);
        *(uint4*)(g_hist2 + hbase) = make_uint4(0u, 0u, 0u, 0u);
        if (tid == 0) {
            const double rowtot = atomicAdd(&g_rowsum[b], 0.0) + tie
                                + g_locr[b] + g_pcer[b];
            atomicAdd(&g_fsum, rowtot);
            atomicAdd(&g_fnp, np);
            g_rowsum[b] = 0.0; g_arr1[b] = 0; g_arr2[b] = 0;
            g_locr[b] = 0.0;   g_pcer[b] = 0.0; g_numpos[b] = 0;
            __threadfence();
            const int tk = atomicAdd(&g_ticket, 1);
            if (tk == BB - 1) {          // global last finisher
                const double fs = atomicAdd(&g_fsum, 0.0);
                const int    fn = atomicAdd(&g_fnp, 0);
                out[0] = (float)(fs / (double)fn);
                g_fsum = 0.0; g_fnp = 0; g_ticket = 0;
                __threadfence();
            }
        }
    }
}

// ---------------- launch (2 kernels) ----------------
extern "C" void kernel_launch(void* const* d_in, const int* in_sizes, int n_in,
                              void* d_out, int out_size)
{
    const float* loc_p = (const float*)d_in[0];
    const float* loc_t = (const float*)d_in[1];
    const float* cls_p = (const float*)d_in[2];
    const int*   cls_t = (const int*)d_in[3];

    dim3 grid1(AA / TILE, BB);
    ce_kernel<<<grid1, TILE>>>(loc_p, loc_t, cls_p, cls_t);
    dim3 grid2(NSPLIT, BB);
    select_kernel<<<grid2, 1024>>>((float*)d_out);
}